// round 1
// baseline (speedup 1.0000x reference)
#include <cuda_runtime.h>
#include <math.h>

#define NN      4096
#define INDIM   256
#define ODIM    256
#define HEADS   4
#define HDIM    64

// -------- scratch (no allocations allowed) --------
__device__ float g_hcat [NN * ODIM];    // h concat: [n][h*64+k]
__device__ float g_resid[NN * ODIM];    // x@Wr + br
__device__ float g_scol [HEADS * NN];   // a1 . h   (column/j contribution)
__device__ float g_srow [HEADS * NN];   // a2 . h   (row/i contribution)
__device__ float g_gmax [HEADS];        // per-head global max of s_col

// ============================================================
// Kernel 1: fused GEMM  out[4096][512]
//   cols 0..255  -> g_hcat  (x @ Wcat), Wcat[d][c] = W[c/64][d][c%64]
//   cols 256..511-> g_resid (x @ Wr + br)
// BM=64 BN=64 BK=16, 256 threads, 4x4 micro-tile
// ============================================================
__global__ __launch_bounds__(256) void k_gemm(
    const float* __restrict__ x, const float* __restrict__ W,
    const float* __restrict__ Wr, const float* __restrict__ br)
{
    __shared__ float As[16][68];
    __shared__ float Bs[16][68];
    const int tid = threadIdx.x;
    const int tx = tid & 15, ty = tid >> 4;
    const int m0 = blockIdx.y * 64;
    const int n0 = blockIdx.x * 64;

    float acc[4][4];
    #pragma unroll
    for (int i = 0; i < 4; i++)
        #pragma unroll
        for (int j = 0; j < 4; j++) acc[i][j] = 0.f;

    for (int k0 = 0; k0 < INDIM; k0 += 16) {
        #pragma unroll
        for (int q = 0; q < 4; q++) {              // A tile 64x16
            int idx = tid + q * 256;
            int r = idx >> 4, kk = idx & 15;
            As[kk][r] = x[(m0 + r) * INDIM + k0 + kk];
        }
        #pragma unroll
        for (int q = 0; q < 4; q++) {              // B tile 16x64
            int idx = tid + q * 256;
            int kk = idx >> 6, c = idx & 63;
            int cg = n0 + c;
            float v;
            if (cg < ODIM)
                v = W[(cg >> 6) * (INDIM * HDIM) + (k0 + kk) * HDIM + (cg & 63)];
            else
                v = Wr[(k0 + kk) * ODIM + (cg - ODIM)];
            Bs[kk][c] = v;
        }
        __syncthreads();
        #pragma unroll
        for (int kk = 0; kk < 16; kk++) {
            float a[4], b[4];
            #pragma unroll
            for (int i = 0; i < 4; i++) a[i] = As[kk][ty * 4 + i];
            #pragma unroll
            for (int j = 0; j < 4; j++) b[j] = Bs[kk][tx * 4 + j];
            #pragma unroll
            for (int i = 0; i < 4; i++)
                #pragma unroll
                for (int j = 0; j < 4; j++) acc[i][j] += a[i] * b[j];
        }
        __syncthreads();
    }
    #pragma unroll
    for (int i = 0; i < 4; i++) {
        int rg = m0 + ty * 4 + i;
        #pragma unroll
        for (int j = 0; j < 4; j++) {
            int cg = n0 + tx * 4 + j;
            if (cg < ODIM) g_hcat[rg * ODIM + cg] = acc[i][j];
            else           g_resid[rg * ODIM + (cg - ODIM)] = acc[i][j] + br[cg - ODIM];
        }
    }
}

// ============================================================
// Kernel 2: s_col[h][n] = h . a1,  s_row[h][n] = h . a2
// block = 32 rows, 256 threads
// ============================================================
__global__ __launch_bounds__(256) void k_scores(
    const float* __restrict__ a1, const float* __restrict__ a2)
{
    __shared__ float hs[32 * 256];
    const int tid = threadIdx.x;
    const int i0 = blockIdx.x * 32;
    #pragma unroll
    for (int q = 0; q < 32; q++)
        hs[tid + q * 256] = g_hcat[i0 * ODIM + tid + q * 256];
    __syncthreads();
    if (tid < 128) {
        int r = tid >> 2, h = tid & 3;
        int lane = tid & 31;
        float s1 = 0.f, s2 = 0.f;
        #pragma unroll
        for (int k0 = 0; k0 < HDIM; k0++) {
            int k = (k0 + lane) & 63;              // bank-rotate
            float hv = hs[r * 256 + h * 64 + k];
            s1 += hv * a1[h * 64 + k];
            s2 += hv * a2[h * 64 + k];
        }
        g_scol[h * NN + i0 + r] = s1;
        g_srow[h * NN + i0 + r] = s2;
    }
}

// ============================================================
// Kernel 2b: per-head global max of s_col (single block)
// ============================================================
__global__ __launch_bounds__(256) void k_gmax()
{
    __shared__ float red[256];
    const int tid = threadIdx.x;
    const int h = tid >> 6, l = tid & 63;
    float m = -1e30f;
    for (int n = l; n < NN; n += 64)
        m = fmaxf(m, g_scol[h * NN + n]);
    red[tid] = m;
    __syncthreads();
    for (int s = 32; s >= 1; s >>= 1) {
        if (l < s) red[tid] = fmaxf(red[tid], red[tid + s]);
        __syncthreads();
    }
    if (l == 0) g_gmax[h] = red[tid];
}

// ============================================================
// Kernel 3: fused masked-softmax attention + PV + ELU + residual + LayerNorm
// One block = 32 rows x all 256 cols. 256 threads, thread = one column.
// Single pass over adj; safe max m[h,i] = lrelu(s_row + gmax[h]).
// smem: hsm 32KB (h tile, reused as y), psm 16KB (p tile, reused as denoms)
// ============================================================
__global__ __launch_bounds__(256) void k_attn(
    const int* __restrict__ adj,
    const float* __restrict__ gamma, const float* __restrict__ beta,
    float* __restrict__ out)
{
    __shared__ float hsm[32 * 256];   // 32 KB
    __shared__ float psm[32 * 128];   // 16 KB : [r][hh][jj]

    const int tid = threadIdx.x;
    const int i0  = blockIdx.x * 32;
    const int c   = tid;              // output column
    const int hd  = c >> 6;           // this column's head

    // p-producer decode (idx = tid + k*256 -> r=(tid>>7)+2k, hh, jj fixed)
    const int hh_p  = (tid >> 5) & 3;
    const int jj_p  = tid & 31;
    const int rbase = tid >> 7;

    float si16[16], m16[16];
    {
        float gm = g_gmax[hh_p];
        #pragma unroll
        for (int k = 0; k < 16; k++) {
            float si = g_srow[hh_p * NN + i0 + rbase + 2 * k];
            si16[k] = si;
            float mm = si + gm;
            m16[k] = mm > 0.f ? mm : 0.2f * mm;
        }
    }

    float acc[32];
    #pragma unroll
    for (int r = 0; r < 32; r++) acc[r] = 0.f;
    float denom = 0.f;                 // valid for tid<128: (r=tid>>2, h=tid&3)

    for (int j0 = 0; j0 < NN; j0 += 32) {
        // --- stage h tile (rows j0..j0+31 are contiguous) ---
        #pragma unroll
        for (int q = 0; q < 8; q++) {
            int lin = tid + q * 256 * 4;     // float4 granularity
            ((float4*)hsm)[tid + q * 256] =
                ((const float4*)(g_hcat + j0 * ODIM))[tid + q * 256];
            (void)lin;
        }
        // --- compute p tile ---
        float sj = g_scol[hh_p * NN + j0 + jj_p];
        #pragma unroll
        for (int k = 0; k < 16; k++) {
            int adjv = adj[(i0 + rbase + 2 * k) * NN + j0 + jj_p];
            float e = si16[k] + sj;
            e = e > 0.f ? e : 0.2f * e;
            float p = (adjv > 0) ? __expf(e - m16[k]) : 0.f;
            psm[tid + k * 256] = p;
        }
        __syncthreads();

        // --- PV accumulate: acc[r] += p[r][hd][jj] * h[jj][c] ---
        #pragma unroll 8
        for (int jj = 0; jj < 32; jj++) {
            float hv = hsm[jj * 256 + c];
            #pragma unroll
            for (int r = 0; r < 32; r++)
                acc[r] += psm[r * 128 + hd * 32 + jj] * hv;
        }
        // --- denominator partial sums (128 threads, bank-rotated) ---
        if (tid < 128) {
            int r = tid >> 2, hh = tid & 3;
            int base = r * 128 + hh * 32;
            float s = 0.f;
            #pragma unroll
            for (int jj = 0; jj < 32; jj++)
                s += psm[base + ((jj + tid) & 31)];
            denom += s;
        }
        __syncthreads();
    }

    // --- publish denominators (reuse psm) ---
    if (tid < 128) psm[tid] = denom;   // psm[r*4 + h]
    __syncthreads();

    // --- y = elu(att_out) + resid, staged into hsm ---
    #pragma unroll
    for (int r = 0; r < 32; r++) {
        float d = psm[r * 4 + hd];
        float v = acc[r] / d;
        v = v > 0.f ? v : (__expf(v) - 1.f);       // ELU
        v += g_resid[(i0 + r) * ODIM + c];
        hsm[r * 256 + c] = v;
    }
    __syncthreads();

    // --- LayerNorm: warp w handles rows 4w..4w+3 ---
    const int w = tid >> 5, lane = tid & 31;
    #pragma unroll
    for (int rr = 0; rr < 4; rr++) {
        int r = w * 4 + rr;
        float s = 0.f, sq = 0.f;
        #pragma unroll
        for (int q = 0; q < 8; q++) {
            float v = hsm[r * 256 + lane + q * 32];
            s += v; sq += v * v;
        }
        #pragma unroll
        for (int o = 16; o > 0; o >>= 1) {
            s  += __shfl_xor_sync(0xFFFFFFFFu, s,  o);
            sq += __shfl_xor_sync(0xFFFFFFFFu, sq, o);
        }
        float mu  = s * (1.f / 256.f);
        float var = sq * (1.f / 256.f) - mu * mu;
        float rstd = rsqrtf(var + 1e-5f);
        #pragma unroll
        for (int q = 0; q < 8; q++) {
            int cc = lane + q * 32;
            float v = hsm[r * 256 + cc];
            out[(i0 + r) * ODIM + cc] = (v - mu) * rstd * gamma[cc] + beta[cc];
        }
    }
}

// ============================================================
extern "C" void kernel_launch(void* const* d_in, const int* in_sizes, int n_in,
                              void* d_out, int out_size)
{
    const float* x     = (const float*)d_in[0];
    const int*   adj   = (const int*)  d_in[1];
    const float* W     = (const float*)d_in[2];
    const float* a1    = (const float*)d_in[3];
    const float* a2    = (const float*)d_in[4];
    const float* Wr    = (const float*)d_in[5];
    const float* br    = (const float*)d_in[6];
    const float* gamma = (const float*)d_in[7];
    const float* beta  = (const float*)d_in[8];
    float* out = (float*)d_out;

    k_gemm  <<<dim3(512 / 64, NN / 64), 256>>>(x, W, Wr, br);
    k_scores<<<NN / 32, 256>>>(a1, a2);
    k_gmax  <<<1, 256>>>();
    k_attn  <<<NN / 32, 256>>>(adj, gamma, beta, out);
}

// round 4
// speedup vs baseline: 1.2425x; 1.2425x over previous
#include <cuda_runtime.h>
#include <math.h>

#define NN      4096
#define INDIM   256
#define ODIM    256
#define HEADS   4
#define HDIM    64
#define SPLITS  4
#define JCHUNK  (NN / SPLITS)     // 1024
#define JT      16                // j-tile rows
#define PITCH   36                // psm pitch (floats): 16B-aligned rows

// -------- scratch (no allocations allowed) --------
__device__ float g_hcat [NN * ODIM];          // h concat: [n][h*64+k]
__device__ float g_resid[NN * ODIM];          // x@Wr + br
__device__ float g_scol [HEADS * NN];         // a1 . h
__device__ float g_srow [HEADS * NN];         // a2 . h
__device__ float g_gmax [HEADS];              // per-head global max of s_col
__device__ float g_pacc [SPLITS * NN * ODIM]; // partial PV numerators
__device__ float g_pden [SPLITS * HEADS * NN];// partial softmax denominators

// ============================================================
// Kernel 1: fused GEMM  out[4096][512]
//   cols 0..255   -> g_hcat  (x @ Wcat)
//   cols 256..511 -> g_resid (x @ Wr + br)
// ============================================================
__global__ __launch_bounds__(256) void k_gemm(
    const float* __restrict__ x, const float* __restrict__ W,
    const float* __restrict__ Wr, const float* __restrict__ br)
{
    __shared__ float As[16][68];
    __shared__ float Bs[16][68];
    const int tid = threadIdx.x;
    const int tx = tid & 15, ty = tid >> 4;
    const int m0 = blockIdx.y * 64;
    const int n0 = blockIdx.x * 64;

    float acc[4][4];
    #pragma unroll
    for (int i = 0; i < 4; i++)
        #pragma unroll
        for (int j = 0; j < 4; j++) acc[i][j] = 0.f;

    for (int k0 = 0; k0 < INDIM; k0 += 16) {
        #pragma unroll
        for (int q = 0; q < 4; q++) {
            int idx = tid + q * 256;
            int r = idx >> 4, kk = idx & 15;
            As[kk][r] = x[(m0 + r) * INDIM + k0 + kk];
        }
        #pragma unroll
        for (int q = 0; q < 4; q++) {
            int idx = tid + q * 256;
            int kk = idx >> 6, c = idx & 63;
            int cg = n0 + c;
            float v;
            if (cg < ODIM)
                v = W[(cg >> 6) * (INDIM * HDIM) + (k0 + kk) * HDIM + (cg & 63)];
            else
                v = Wr[(k0 + kk) * ODIM + (cg - ODIM)];
            Bs[kk][c] = v;
        }
        __syncthreads();
        #pragma unroll
        for (int kk = 0; kk < 16; kk++) {
            float a[4], b[4];
            #pragma unroll
            for (int i = 0; i < 4; i++) a[i] = As[kk][ty * 4 + i];
            #pragma unroll
            for (int j = 0; j < 4; j++) b[j] = Bs[kk][tx * 4 + j];
            #pragma unroll
            for (int i = 0; i < 4; i++)
                #pragma unroll
                for (int j = 0; j < 4; j++) acc[i][j] += a[i] * b[j];
        }
        __syncthreads();
    }
    #pragma unroll
    for (int i = 0; i < 4; i++) {
        int rg = m0 + ty * 4 + i;
        #pragma unroll
        for (int j = 0; j < 4; j++) {
            int cg = n0 + tx * 4 + j;
            if (cg < ODIM) g_hcat[rg * ODIM + cg] = acc[i][j];
            else           g_resid[rg * ODIM + (cg - ODIM)] = acc[i][j] + br[cg - ODIM];
        }
    }
}

// ============================================================
// Kernel 2: s_col / s_row
// ============================================================
__global__ __launch_bounds__(256) void k_scores(
    const float* __restrict__ a1, const float* __restrict__ a2)
{
    __shared__ float hs[32 * 256];
    const int tid = threadIdx.x;
    const int i0 = blockIdx.x * 32;
    #pragma unroll
    for (int q = 0; q < 32; q++)
        hs[tid + q * 256] = g_hcat[i0 * ODIM + tid + q * 256];
    __syncthreads();
    if (tid < 128) {
        int r = tid >> 2, h = tid & 3;
        int lane = tid & 31;
        float s1 = 0.f, s2 = 0.f;
        #pragma unroll
        for (int k0 = 0; k0 < HDIM; k0++) {
            int k = (k0 + lane) & 63;
            float hv = hs[r * 256 + h * 64 + k];
            s1 += hv * a1[h * 64 + k];
            s2 += hv * a2[h * 64 + k];
        }
        g_scol[h * NN + i0 + r] = s1;
        g_srow[h * NN + i0 + r] = s2;
    }
}

// ============================================================
// Kernel 2b: per-head global max of s_col
// ============================================================
__global__ __launch_bounds__(256) void k_gmax()
{
    __shared__ float red[256];
    const int tid = threadIdx.x;
    const int h = tid >> 6, l = tid & 63;
    float m = -1e30f;
    for (int n = l; n < NN; n += 64)
        m = fmaxf(m, g_scol[h * NN + n]);
    red[tid] = m;
    __syncthreads();
    for (int s = 32; s >= 1; s >>= 1) {
        if (l < s) red[tid] = fmaxf(red[tid], red[tid + s]);
        __syncthreads();
    }
    if (l == 0) g_gmax[h] = red[tid];
}

// ============================================================
// Kernel 3: split-j masked-softmax attention + PV partials
// grid = (128 i-blocks, SPLITS). Block = 32 rows x 256 cols, 256 threads.
// j-tile = 16. psm layout: [head][jj][r] pitch 36 -> 16B-aligned rows for
// float4 broadcast loads (1 wavefront per warp per load).
// static smem: hsm 16KB + psm 9KB = 25.6KB -> 2 blocks/SM.
// ============================================================
__global__ __launch_bounds__(256, 2) void k_attn(
    const int* __restrict__ adj)
{
    __shared__ __align__(16) float hsm[JT * 256];          // 16 KB
    __shared__ __align__(16) float psm[HEADS * JT * PITCH];// 9 KB

    const int tid  = threadIdx.x;
    const int i0   = blockIdx.x * 32;
    const int sOff = blockIdx.y * JCHUNK;
    const int c    = tid;
    const int hd   = c >> 6;

    // producer decode: thread = (rgroup, hh, jj); each covers 8 rows of p
    const int jj_p  = tid & 15;
    const int hh    = (tid >> 4) & 3;
    const int rbase = (tid >> 6) * 8;

    float si[8], m8[8];
    {
        float gm = g_gmax[hh];
        #pragma unroll
        for (int k = 0; k < 8; k++) {
            float s = g_srow[hh * NN + i0 + rbase + k];
            si[k] = s;
            float mm = s + gm;
            m8[k] = mm > 0.f ? mm : 0.2f * mm;
        }
    }

    float acc[32];
    #pragma unroll
    for (int k = 0; k < 32; k++) acc[k] = 0.f;
    float denom = 0.f;                 // valid for tid<128
    const int hh_d = tid & 3;
    const int r_d  = tid >> 2;

    for (int t = 0; t < JCHUNK / JT; t++) {
        const int j0 = sOff + t * JT;

        // --- stage h tile (16 rows x 256 cols) ---
        {
            const float4* src = (const float4*)(g_hcat + (size_t)j0 * ODIM);
            float4* dst = (float4*)hsm;
            #pragma unroll
            for (int q = 0; q < 4; q++)
                dst[tid + q * 256] = src[tid + q * 256];
        }
        // --- produce p tile (transposed layout) ---
        {
            float sj = g_scol[hh * NN + j0 + jj_p];
            const int* arow = adj + (size_t)(i0 + rbase) * NN + j0 + jj_p;
            float* pdst = psm + (hh * JT + jj_p) * PITCH + rbase;
            #pragma unroll
            for (int k = 0; k < 8; k++) {
                int av = arow[(size_t)k * NN];
                float e = si[k] + sj;
                e = e > 0.f ? e : 0.2f * e;
                float p = (av > 0) ? __expf(e - m8[k]) : 0.f;
                pdst[k] = p;
            }
        }
        __syncthreads();

        // --- PV accumulate: float4 broadcast p loads + scalar FFMA ---
        const float* pbase = psm + hd * JT * PITCH;
        #pragma unroll 4
        for (int jj = 0; jj < JT; jj++) {
            float hv = hsm[jj * 256 + c];
            const float4* prow = (const float4*)(pbase + jj * PITCH);
            #pragma unroll
            for (int u = 0; u < 8; u++) {
                float4 pv = prow[u];              // p[4u..4u+3] broadcast
                acc[4 * u + 0] += pv.x * hv;
                acc[4 * u + 1] += pv.y * hv;
                acc[4 * u + 2] += pv.z * hv;
                acc[4 * u + 3] += pv.w * hv;
            }
        }
        // --- denominator partial sums ---
        if (tid < 128) {
            float s = 0.f;
            #pragma unroll
            for (int q = 0; q < JT; q++) {
                int j = (q + r_d) & (JT - 1);
                s += psm[(hh_d * JT + j) * PITCH + r_d];
            }
            denom += s;
        }
        __syncthreads();
    }

    // --- write partials ---
    {
        float* outp = g_pacc + ((size_t)blockIdx.y * NN + i0) * ODIM + c;
        #pragma unroll
        for (int k = 0; k < 32; k++)
            outp[(size_t)k * ODIM] = acc[k];
    }
    if (tid < 128)
        g_pden[((size_t)blockIdx.y * HEADS + hh_d) * NN + i0 + r_d] = denom;
}

// ============================================================
// Kernel 4: reduce splits + softmax div + ELU + residual + LayerNorm
// ============================================================
__global__ __launch_bounds__(256) void k_final(
    const float* __restrict__ gamma, const float* __restrict__ beta,
    float* __restrict__ out)
{
    __shared__ float ysm[32 * 256];
    __shared__ float densm[32 * 4];
    const int tid = threadIdx.x;
    const int i0 = blockIdx.x * 32;
    const int c = tid;
    const int hd = c >> 6;

    if (tid < 128) {
        int hh = tid & 3, r = tid >> 2;
        float d = 0.f;
        #pragma unroll
        for (int s = 0; s < SPLITS; s++)
            d += g_pden[((size_t)s * HEADS + hh) * NN + i0 + r];
        densm[r * 4 + hh] = d;
    }
    __syncthreads();

    #pragma unroll 4
    for (int r = 0; r < 32; r++) {
        float a = 0.f;
        #pragma unroll
        for (int s = 0; s < SPLITS; s++)
            a += g_pacc[((size_t)s * NN + i0 + r) * ODIM + c];
        float v = a / densm[r * 4 + hd];
        v = v > 0.f ? v : (__expf(v) - 1.f);        // ELU
        v += g_resid[(size_t)(i0 + r) * ODIM + c];
        ysm[r * 256 + c] = v;
    }
    __syncthreads();

    const int w = tid >> 5, lane = tid & 31;
    #pragma unroll
    for (int rr = 0; rr < 4; rr++) {
        int r = w * 4 + rr;
        float s = 0.f, sq = 0.f;
        #pragma unroll
        for (int q = 0; q < 8; q++) {
            float v = ysm[r * 256 + lane + q * 32];
            s += v; sq += v * v;
        }
        #pragma unroll
        for (int o = 16; o > 0; o >>= 1) {
            s  += __shfl_xor_sync(0xFFFFFFFFu, s,  o);
            sq += __shfl_xor_sync(0xFFFFFFFFu, sq, o);
        }
        float mu   = s * (1.f / 256.f);
        float var  = sq * (1.f / 256.f) - mu * mu;
        float rstd = rsqrtf(var + 1e-5f);
        #pragma unroll
        for (int q = 0; q < 8; q++) {
            int cc = lane + q * 32;
            float v = ysm[r * 256 + cc];
            out[(size_t)(i0 + r) * ODIM + cc] = (v - mu) * rstd * gamma[cc] + beta[cc];
        }
    }
}

// ============================================================
extern "C" void kernel_launch(void* const* d_in, const int* in_sizes, int n_in,
                              void* d_out, int out_size)
{
    const float* x     = (const float*)d_in[0];
    const int*   adj   = (const int*)  d_in[1];
    const float* W     = (const float*)d_in[2];
    const float* a1    = (const float*)d_in[3];
    const float* a2    = (const float*)d_in[4];
    const float* Wr    = (const float*)d_in[5];
    const float* br    = (const float*)d_in[6];
    const float* gamma = (const float*)d_in[7];
    const float* beta  = (const float*)d_in[8];
    float* out = (float*)d_out;

    k_gemm  <<<dim3(512 / 64, NN / 64), 256>>>(x, W, Wr, br);
    k_scores<<<NN / 32, 256>>>(a1, a2);
    k_gmax  <<<1, 256>>>();
    k_attn  <<<dim3(NN / 32, SPLITS), 256>>>(adj);
    k_final <<<NN / 32, 256>>>(gamma, beta, out);
}

// round 5
// speedup vs baseline: 1.9180x; 1.5436x over previous
#include <cuda_runtime.h>
#include <math.h>

#define NN      4096
#define INDIM   256
#define ODIM    256
#define HEADS   4
#define HDIM    64
#define SPLITS  8
#define JCHUNK  (NN / SPLITS)     // 512
#define JT      16                // j-tile rows
#define PITCH   36                // psm pitch (floats): 16B-aligned rows, 4-way STS conflict

// -------- scratch (no allocations allowed) --------
__device__ float g_hcat [NN * ODIM];          // h concat: [n][h*64+k]
__device__ float g_resid[NN * ODIM];          // x@Wr + br
__device__ float g_scol [HEADS * NN];         // a1 . h
__device__ float g_srow [HEADS * NN];         // a2 . h
__device__ float g_B1   [HEADS * NN];         // exp(s_col)
__device__ float g_B2   [HEADS * NN];         // exp(0.2*s_col)
__device__ float g_gmax [HEADS];              // per-head global max of s_col
__device__ float g_pacc [SPLITS * NN * ODIM]; // partial PV numerators (33.5MB)
__device__ float g_pden [SPLITS * HEADS * NN];// partial softmax denominators

// ============================================================
// Kernel 1: fused GEMM  out[4096][512]
//   cols 0..255   -> g_hcat  (x @ Wcat)
//   cols 256..511 -> g_resid (x @ Wr + br)
// ============================================================
__global__ __launch_bounds__(256) void k_gemm(
    const float* __restrict__ x, const float* __restrict__ W,
    const float* __restrict__ Wr, const float* __restrict__ br)
{
    __shared__ float As[16][68];
    __shared__ float Bs[16][68];
    const int tid = threadIdx.x;
    const int tx = tid & 15, ty = tid >> 4;
    const int m0 = blockIdx.y * 64;
    const int n0 = blockIdx.x * 64;

    float acc[4][4];
    #pragma unroll
    for (int i = 0; i < 4; i++)
        #pragma unroll
        for (int j = 0; j < 4; j++) acc[i][j] = 0.f;

    for (int k0 = 0; k0 < INDIM; k0 += 16) {
        #pragma unroll
        for (int q = 0; q < 4; q++) {
            int idx = tid + q * 256;
            int r = idx >> 4, kk = idx & 15;
            As[kk][r] = x[(m0 + r) * INDIM + k0 + kk];
        }
        #pragma unroll
        for (int q = 0; q < 4; q++) {
            int idx = tid + q * 256;
            int kk = idx >> 6, c = idx & 63;
            int cg = n0 + c;
            float v;
            if (cg < ODIM)
                v = W[(cg >> 6) * (INDIM * HDIM) + (k0 + kk) * HDIM + (cg & 63)];
            else
                v = Wr[(k0 + kk) * ODIM + (cg - ODIM)];
            Bs[kk][c] = v;
        }
        __syncthreads();
        #pragma unroll
        for (int kk = 0; kk < 16; kk++) {
            float a[4], b[4];
            #pragma unroll
            for (int i = 0; i < 4; i++) a[i] = As[kk][ty * 4 + i];
            #pragma unroll
            for (int j = 0; j < 4; j++) b[j] = Bs[kk][tx * 4 + j];
            #pragma unroll
            for (int i = 0; i < 4; i++)
                #pragma unroll
                for (int j = 0; j < 4; j++) acc[i][j] += a[i] * b[j];
        }
        __syncthreads();
    }
    #pragma unroll
    for (int i = 0; i < 4; i++) {
        int rg = m0 + ty * 4 + i;
        #pragma unroll
        for (int j = 0; j < 4; j++) {
            int cg = n0 + tx * 4 + j;
            if (cg < ODIM) g_hcat[rg * ODIM + cg] = acc[i][j];
            else           g_resid[rg * ODIM + (cg - ODIM)] = acc[i][j] + br[cg - ODIM];
        }
    }
}

// ============================================================
// Kernel 2: s_col / s_row + B1/B2 = exp(s_col), exp(0.2 s_col)
// ============================================================
__global__ __launch_bounds__(256) void k_scores(
    const float* __restrict__ a1, const float* __restrict__ a2)
{
    __shared__ float hs[32 * 256];
    const int tid = threadIdx.x;
    const int i0 = blockIdx.x * 32;
    #pragma unroll
    for (int q = 0; q < 32; q++)
        hs[tid + q * 256] = g_hcat[i0 * ODIM + tid + q * 256];
    __syncthreads();
    if (tid < 128) {
        int r = tid >> 2, h = tid & 3;
        int lane = tid & 31;
        float s1 = 0.f, s2 = 0.f;
        #pragma unroll
        for (int k0 = 0; k0 < HDIM; k0++) {
            int k = (k0 + lane) & 63;
            float hv = hs[r * 256 + h * 64 + k];
            s1 += hv * a1[h * 64 + k];
            s2 += hv * a2[h * 64 + k];
        }
        g_scol[h * NN + i0 + r] = s1;
        g_srow[h * NN + i0 + r] = s2;
        g_B1  [h * NN + i0 + r] = __expf(s1);
        g_B2  [h * NN + i0 + r] = __expf(0.2f * s1);
    }
}

// ============================================================
// Kernel 2b: per-head global max of s_col
// ============================================================
__global__ __launch_bounds__(256) void k_gmax()
{
    __shared__ float red[256];
    const int tid = threadIdx.x;
    const int h = tid >> 6, l = tid & 63;
    float m = -1e30f;
    for (int n = l; n < NN; n += 64)
        m = fmaxf(m, g_scol[h * NN + n]);
    red[tid] = m;
    __syncthreads();
    for (int s = 32; s >= 1; s >>= 1) {
        if (l < s) red[tid] = fmaxf(red[tid], red[tid + s]);
        __syncthreads();
    }
    if (l == 0) g_gmax[h] = red[tid];
}

// ============================================================
// Kernel 3: split-j attention + PV partials. NO exp in hot loop:
//   p = adj ? ((si+sj>0) ? A1_i*B1_j : A2_i*B2_j) : 0
// grid = (128 i-blocks, SPLITS). 256 threads.
// Producer: thread=(rgroup of 8 rows, hh, jj). p kept in regs -> 2x STS.128.
// Consumer: thread = 16 rows x 2 cols, one head per warp:
//   per jj: 4x LDS.128 broadcast (p) + 1x LDS.64 (hv) + 32 FFMA.
// Denominator accumulated in producer regs; one shfl reduce at end.
// ============================================================
__global__ __launch_bounds__(256, 2) void k_attn(
    const int* __restrict__ adj)
{
    __shared__ __align__(16) float hsm[JT * 256];            // 16 KB
    __shared__ __align__(16) float psm[HEADS * JT * PITCH];  // 9.2 KB

    const int tid  = threadIdx.x;
    const int i0   = blockIdx.x * 32;
    const int sOff = blockIdx.y * JCHUNK;

    // ---- producer mapping ----
    const int jj_p  = tid & 15;
    const int hh    = (tid >> 4) & 3;
    const int rbase = (tid >> 6) * 8;

    // ---- consumer mapping ----
    const int cg = tid & 127;
    const int c0 = 2 * cg;
    const int r0 = (tid >> 7) * 16;
    const int hd = cg >> 5;

    float si8[8], A1r[8], A2r[8], den8[8];
    {
        float gm = g_gmax[hh];
        #pragma unroll
        for (int k = 0; k < 8; k++) {
            float s = g_srow[hh * NN + i0 + rbase + k];
            si8[k] = s;
            float mm = s + gm;
            mm = mm > 0.f ? mm : 0.2f * mm;            // safe row max
            A1r[k] = __expf(s - mm);
            A2r[k] = __expf(0.2f * s - mm);
            den8[k] = 0.f;
        }
    }

    float2 acc[16];
    #pragma unroll
    for (int k = 0; k < 16; k++) acc[k] = make_float2(0.f, 0.f);

    for (int t = 0; t < JCHUNK / JT; t++) {
        const int j0 = sOff + t * JT;

        // --- stage h tile (16 rows x 256 cols) ---
        {
            const float4* src = (const float4*)(g_hcat + (size_t)j0 * ODIM);
            float4* dst = (float4*)hsm;
            #pragma unroll
            for (int q = 0; q < 4; q++)
                dst[tid + q * 256] = src[tid + q * 256];
        }
        // --- produce p tile (registers -> 2x STS.128) ---
        {
            float sj  = g_scol[hh * NN + j0 + jj_p];
            float B1j = g_B1  [hh * NN + j0 + jj_p];
            float B2j = g_B2  [hh * NN + j0 + jj_p];
            const int* arow = adj + (size_t)(i0 + rbase) * NN + j0 + jj_p;
            float p8[8];
            #pragma unroll
            for (int k = 0; k < 8; k++) {
                int av = arow[(size_t)k * NN];
                bool pos = (si8[k] + sj) > 0.f;
                float tA = pos ? A1r[k] : A2r[k];
                float tB = pos ? B1j : B2j;
                float p = tA * tB;
                p = (av > 0) ? p : 0.f;
                p8[k] = p;
                den8[k] += p;
            }
            float* pdst = psm + (hh * JT + jj_p) * PITCH + rbase;
            *(float4*)(pdst)     = make_float4(p8[0], p8[1], p8[2], p8[3]);
            *(float4*)(pdst + 4) = make_float4(p8[4], p8[5], p8[6], p8[7]);
        }
        __syncthreads();

        // --- PV accumulate ---
        #pragma unroll 4
        for (int jj = 0; jj < JT; jj++) {
            float2 hv = *(const float2*)(hsm + jj * 256 + c0);
            const float4* prow = (const float4*)(psm + (hd * JT + jj) * PITCH + r0);
            float4 p0 = prow[0], p1 = prow[1], p2 = prow[2], p3 = prow[3];
            acc[0].x  += p0.x * hv.x;  acc[0].y  += p0.x * hv.y;
            acc[1].x  += p0.y * hv.x;  acc[1].y  += p0.y * hv.y;
            acc[2].x  += p0.z * hv.x;  acc[2].y  += p0.z * hv.y;
            acc[3].x  += p0.w * hv.x;  acc[3].y  += p0.w * hv.y;
            acc[4].x  += p1.x * hv.x;  acc[4].y  += p1.x * hv.y;
            acc[5].x  += p1.y * hv.x;  acc[5].y  += p1.y * hv.y;
            acc[6].x  += p1.z * hv.x;  acc[6].y  += p1.z * hv.y;
            acc[7].x  += p1.w * hv.x;  acc[7].y  += p1.w * hv.y;
            acc[8].x  += p2.x * hv.x;  acc[8].y  += p2.x * hv.y;
            acc[9].x  += p2.y * hv.x;  acc[9].y  += p2.y * hv.y;
            acc[10].x += p2.z * hv.x;  acc[10].y += p2.z * hv.y;
            acc[11].x += p2.w * hv.x;  acc[11].y += p2.w * hv.y;
            acc[12].x += p3.x * hv.x;  acc[12].y += p3.x * hv.y;
            acc[13].x += p3.y * hv.x;  acc[13].y += p3.y * hv.y;
            acc[14].x += p3.z * hv.x;  acc[14].y += p3.z * hv.y;
            acc[15].x += p3.w * hv.x;  acc[15].y += p3.w * hv.y;
        }
        __syncthreads();
    }

    // --- write PV partials (float2, coalesced) ---
    {
        float* outp = g_pacc + ((size_t)blockIdx.y * NN + i0 + r0) * ODIM + c0;
        #pragma unroll
        for (int k = 0; k < 16; k++)
            *(float2*)(outp + (size_t)k * ODIM) = acc[k];
    }
    // --- reduce denominators across the 16 jj lanes ---
    #pragma unroll
    for (int k = 0; k < 8; k++) {
        #pragma unroll
        for (int m = 1; m < 16; m <<= 1)
            den8[k] += __shfl_xor_sync(0xFFFFFFFFu, den8[k], m);
    }
    if ((tid & 15) == 0) {
        #pragma unroll
        for (int k = 0; k < 8; k++)
            g_pden[((size_t)blockIdx.y * HEADS + hh) * NN + i0 + rbase + k] = den8[k];
    }
}

// ============================================================
// Kernel 4: reduce splits + softmax div + ELU + residual + LayerNorm
// ============================================================
__global__ __launch_bounds__(256) void k_final(
    const float* __restrict__ gamma, const float* __restrict__ beta,
    float* __restrict__ out)
{
    __shared__ float ysm[32 * 256];
    __shared__ float densm[32 * 4];
    const int tid = threadIdx.x;
    const int i0 = blockIdx.x * 32;
    const int c = tid;
    const int hd = c >> 6;

    if (tid < 128) {
        int hh = tid & 3, r = tid >> 2;
        float d = 0.f;
        #pragma unroll
        for (int s = 0; s < SPLITS; s++)
            d += g_pden[((size_t)s * HEADS + hh) * NN + i0 + r];
        densm[r * 4 + hh] = d;
    }
    __syncthreads();

    #pragma unroll 4
    for (int r = 0; r < 32; r++) {
        float a = 0.f;
        #pragma unroll
        for (int s = 0; s < SPLITS; s++)
            a += g_pacc[((size_t)s * NN + i0 + r) * ODIM + c];
        float v = a / densm[r * 4 + hd];
        v = v > 0.f ? v : (__expf(v) - 1.f);        // ELU
        v += g_resid[(size_t)(i0 + r) * ODIM + c];
        ysm[r * 256 + c] = v;
    }
    __syncthreads();

    const int w = tid >> 5, lane = tid & 31;
    #pragma unroll
    for (int rr = 0; rr < 4; rr++) {
        int r = w * 4 + rr;
        float s = 0.f, sq = 0.f;
        #pragma unroll
        for (int q = 0; q < 8; q++) {
            float v = ysm[r * 256 + lane + q * 32];
            s += v; sq += v * v;
        }
        #pragma unroll
        for (int o = 16; o > 0; o >>= 1) {
            s  += __shfl_xor_sync(0xFFFFFFFFu, s,  o);
            sq += __shfl_xor_sync(0xFFFFFFFFu, sq, o);
        }
        float mu   = s * (1.f / 256.f);
        float var  = sq * (1.f / 256.f) - mu * mu;
        float rstd = rsqrtf(var + 1e-5f);
        #pragma unroll
        for (int q = 0; q < 8; q++) {
            int cc = lane + q * 32;
            float v = ysm[r * 256 + cc];
            out[(size_t)(i0 + r) * ODIM + cc] = (v - mu) * rstd * gamma[cc] + beta[cc];
        }
    }
}

// ============================================================
extern "C" void kernel_launch(void* const* d_in, const int* in_sizes, int n_in,
                              void* d_out, int out_size)
{
    const float* x     = (const float*)d_in[0];
    const int*   adj   = (const int*)  d_in[1];
    const float* W     = (const float*)d_in[2];
    const float* a1    = (const float*)d_in[3];
    const float* a2    = (const float*)d_in[4];
    const float* Wr    = (const float*)d_in[5];
    const float* br    = (const float*)d_in[6];
    const float* gamma = (const float*)d_in[7];
    const float* beta  = (const float*)d_in[8];
    float* out = (float*)d_out;

    k_gemm  <<<dim3(512 / 64, NN / 64), 256>>>(x, W, Wr, br);
    k_scores<<<NN / 32, 256>>>(a1, a2);
    k_gmax  <<<1, 256>>>();
    k_attn  <<<dim3(NN / 32, SPLITS), 256>>>(adj);
    k_final <<<NN / 32, 256>>>(gamma, beta, out);
}